// round 16
// baseline (speedup 1.0000x reference)
#include <cuda_runtime.h>
#include <math.h>

#define BB    32
#define NN    4096
#define HH    256
#define NNZC  65536
#define PP    64                 // chunks per batch
#define CHUNK 64                 // rows per block

// ---------------- scratch (no cudaMalloc allowed) ----------------
__device__ unsigned char g_validb[BB * NN];   // 0/1 byte mask
__device__ float g_scores[BB * NN];           // masked scores (-inf)
__device__ float g_pm[BB * PP];               // per-chunk max
__device__ float g_pz[BB * PP];               // per-chunk sum exp
__device__ float g_pacc[BB * PP * HH];        // per-chunk weighted x sum

// ---------------- kernels ----------------

__global__ void k_zero() {
    int i = blockIdx.x * blockDim.x + threadIdx.x;
    ((uint4*)g_validb)[i] = make_uint4(0u, 0u, 0u, 0u);
}

// Scatter valid mask; detect int64 vs int32 index dtype on device.
__global__ void k_scatter(const void* __restrict__ bp,
                          const void* __restrict__ rp) {
    __shared__ int s_is64;
    if (threadIdx.x == 0) {
        const unsigned long long* b64 = (const unsigned long long*)bp;
        int ok = 1;
        #pragma unroll
        for (int i = 0; i < 8; i++)
            if (b64[i] >= (unsigned long long)BB) ok = 0;
        s_is64 = ok;
    }
    __syncthreads();
    int i = blockIdx.x * blockDim.x + threadIdx.x;
    int bi, ri;
    if (s_is64) {
        bi = (int)((const long long*)bp)[i];
        ri = (int)((const long long*)rp)[i];
    } else {
        bi = ((const int*)bp)[i];
        ri = ((const int*)rp)[i];
    }
    g_validb[bi * NN + ri] = 1;
}

// Main: one block per (chunk p, batch b). Each warp owns 8 rows.
// Phase 1: stream 8 rows (16 LDG.128 in flight), stage to smem, per-lane
// partial dots; 8 interleaved shuffle-reduce trees; warp 0 also computes s2.
// Phase 2: chunk max -> weights -> weighted accumulation from smem.
// x is read from DRAM exactly once.
__global__ void __launch_bounds__(256, 3)
k_main(const float* __restrict__ x, const float* __restrict__ W,
       const float* __restrict__ bptr) {
    int b = blockIdx.y, p = blockIdx.x;
    int t = threadIdx.x, w = t >> 5, lane = t & 31;

    __shared__ float sx[CHUNK][HH];     // 64 KB staged rows
    __shared__ float sw[CHUNK];         // softmax weights
    __shared__ float red[8], red2[8];
    __shared__ float ss2;

    // W1 in registers: lane covers cols [lane*4, +4) and [128+lane*4, +4)
    float4 wa = *(const float4*)(W + lane * 4);
    float4 wc = *(const float4*)(W + 128 + lane * 4);
    float bias = *bptr;

    int row0 = p * CHUNK + w * 8;
    const float* rp = x + ((size_t)b * NN + row0) * HH + lane * 4;

    // ---- phase 1: load + stage + partial dots (loads fully pipelined) ----
    float pd[8];
    #pragma unroll
    for (int r = 0; r < 8; r++) {
        float4 A = *(const float4*)(rp + (size_t)r * HH);
        float4 C = *(const float4*)(rp + (size_t)r * HH + 128);
        int lr = w * 8 + r;
        *(float4*)&sx[lr][lane * 4]       = A;
        *(float4*)&sx[lr][128 + lane * 4] = C;
        pd[r] = A.x * wa.x + A.y * wa.y + A.z * wa.z + A.w * wa.w
              + C.x * wc.x + C.y * wc.y + C.z * wc.z + C.w * wc.w;
    }

    // warp 0 additionally computes s2 = dot(x[b,0,:], W[H:2H])
    float pd2 = 0.f;
    if (w == 0) {
        const float* r0 = x + (size_t)b * NN * HH + lane * 4;
        float4 A2  = *(const float4*)(r0);
        float4 C2  = *(const float4*)(r0 + 128);
        float4 v2a = *(const float4*)(W + HH + lane * 4);
        float4 v2c = *(const float4*)(W + HH + 128 + lane * 4);
        pd2 = A2.x * v2a.x + A2.y * v2a.y + A2.z * v2a.z + A2.w * v2a.w
            + C2.x * v2c.x + C2.y * v2c.y + C2.z * v2c.z + C2.w * v2c.w;
    }

    // 9 interleaved shuffle-reduce trees (latency overlapped)
    #pragma unroll
    for (int o = 16; o > 0; o >>= 1) {
        #pragma unroll
        for (int r = 0; r < 8; r++)
            pd[r] += __shfl_xor_sync(0xffffffffu, pd[r], o);
        pd2 += __shfl_xor_sync(0xffffffffu, pd2, o);
    }
    if (w == 0 && lane == 0) ss2 = pd2;

    // validity of this warp's 8 consecutive rows: one u64 load
    unsigned long long v8 =
        *(const unsigned long long*)(g_validb + b * NN + row0);

    __syncthreads();
    float s2 = ss2;

    // ---- scores + chunk max ----
    float e[8];
    float me = -INFINITY;
    #pragma unroll
    for (int r = 0; r < 8; r++) {
        int v = (int)((v8 >> (8 * r)) & 1ull);
        float tot = pd[r] + bias + (v ? s2 : 0.f);
        // invalid -> -inf; valid with exact 0 -> -inf (masked_fill(==0))
        e[r] = (v && tot != 0.f) ? tot : -INFINITY;
        me = fmaxf(me, e[r]);
    }
    if (lane == 0) {
        *(float4*)&g_scores[b * NN + row0]     = make_float4(e[0], e[1], e[2], e[3]);
        *(float4*)&g_scores[b * NN + row0 + 4] = make_float4(e[4], e[5], e[6], e[7]);
        red[w] = me;
    }
    __syncthreads();

    float M = red[0];
    #pragma unroll
    for (int i = 1; i < 8; i++) M = fmaxf(M, red[i]);

    float zw = 0.f, wv[8];
    #pragma unroll
    for (int r = 0; r < 8; r++) {
        wv[r] = (e[r] == -INFINITY) ? 0.f : __expf(e[r] - M);
        zw += wv[r];
    }
    if (lane == 0) {
        *(float4*)&sw[w * 8]     = make_float4(wv[0], wv[1], wv[2], wv[3]);
        *(float4*)&sw[w * 8 + 4] = make_float4(wv[4], wv[5], wv[6], wv[7]);
        red2[w] = zw;
    }
    __syncthreads();

    // ---- phase 2: acc[t] = sum_r sw[r] * sx[r][t] (thread t = column) ----
    float a0 = 0.f, a1 = 0.f, a2 = 0.f, a3 = 0.f;
    #pragma unroll
    for (int r = 0; r < CHUNK; r += 4) {
        a0 += sw[r + 0] * sx[r + 0][t];
        a1 += sw[r + 1] * sx[r + 1][t];
        a2 += sw[r + 2] * sx[r + 2][t];
        a3 += sw[r + 3] * sx[r + 3][t];
    }
    g_pacc[(size_t)(b * PP + p) * HH + t] = (a0 + a1) + (a2 + a3);

    if (t == 0) {
        float Z = 0.f;
        #pragma unroll
        for (int i = 0; i < 8; i++) Z += red2[i];
        g_pm[b * PP + p] = M;
        g_pz[b * PP + p] = Z;
    }
}

// Combine PP per-chunk partials per batch; write out[b,:] AND attn[b,:].
__global__ void __launch_bounds__(512)
k_combine(float* __restrict__ out, float* __restrict__ attn, int do_attn) {
    int b = blockIdx.x, t = threadIdx.x;
    __shared__ float sm[PP], sf[PP], szs[PP];
    if (t < PP) { sm[t] = g_pm[b * PP + t]; szs[t] = g_pz[b * PP + t]; }
    __syncthreads();
    float m = -INFINITY;
    #pragma unroll
    for (int q = 0; q < PP; q++) m = fmaxf(m, sm[q]);
    if (t < PP) sf[t] = (sm[t] == -INFINITY) ? 0.f : __expf(sm[t] - m);
    __syncthreads();
    float z = 0.f;
    #pragma unroll
    for (int q = 0; q < PP; q++) z += sf[q] * szs[q];

    if (t < HH) {
        float o = 0.f;
        #pragma unroll
        for (int q = 0; q < PP; q++)
            o += g_pacc[(size_t)(b * PP + q) * HH + t] * sf[q];
        out[b * HH + t] = o / z;
    }
    if (do_attn) {
        float inv = 1.f / z;
        #pragma unroll
        for (int i = t; i < NN; i += 512) {
            float s = g_scores[b * NN + i];
            attn[b * NN + i] = (s == -INFINITY) ? 0.f : __expf(s - m) * inv;
        }
    }
}

// ---------------- launch ----------------
extern "C" void kernel_launch(void* const* d_in, const int* in_sizes, int n_in,
                              void* d_out, int out_size) {
    const float* x    = (const float*)d_in[0];
    const void*  bi   = d_in[1];
    const void*  ri   = d_in[2];
    const float* W    = (const float*)d_in[3];
    const float* bptr = (const float*)d_in[4];
    float* out = (float*)d_out;

    int do_attn = (out_size >= BB * HH + BB * NN) ? 1 : 0;

    k_zero   <<<(BB * NN) / 16 / 256, 256>>>();
    k_scatter<<<NNZC / 256, 256>>>(bi, ri);
    k_main   <<<dim3(PP, BB), 256>>>(x, W, bptr);
    k_combine<<<BB, 512>>>(out, out + BB * HH, do_attn);
}